// round 1
// baseline (speedup 1.0000x reference)
#include <cuda_runtime.h>
#include <math.h>

// ---------------- problem constants ----------------
#define BB    4
#define SS    4096
#define HIDD  1024
#define NHH   16
#define DD    64
#define WINN  512
#define CHUNKK 128
#define NWW   8
#define NCC   32
#define SCALEF 0.125f
#define MTOK  (BB*SS)   // 16384

// ---------------- scratch (device globals; no allocation allowed) ----------------
__device__ float g_q[BB*NHH*SS*DD];
__device__ float g_k[BB*NHH*SS*DD];
__device__ float g_v[BB*NHH*SS*DD];
__device__ float g_attn[BB*SS*HIDD];
__device__ float g_rfak[BB*NHH*NCC*DD];
__device__ float g_rfav[BB*NHH*NCC*DD];

// ---------------- tiled fp32 NT GEMM: C = A(MxK) * B(NxK)^T ----------------
// EPI==0: C row-major MxN.  EPI==1: scatter to (b,h,s,d) layout for q/k/v.
template<int EPI>
__global__ void __launch_bounds__(256) sgemm_nt(const float* __restrict__ A,
                                                const float* __restrict__ Bw,
                                                float* __restrict__ C,
                                                int M, int N, int K) {
    __shared__ __align__(16) float As[16][128];
    __shared__ __align__(16) float Bs[16][128];
    const int tid = threadIdx.x;
    const int m0 = blockIdx.y * 128;
    const int n0 = blockIdx.x * 128;
    const int lr = tid >> 1;            // 0..127
    const int lk = (tid & 1) * 8;       // 0 or 8
    const int tx = tid & 15;
    const int ty = tid >> 4;

    float acc[8][8];
#pragma unroll
    for (int i = 0; i < 8; i++)
#pragma unroll
        for (int j = 0; j < 8; j++) acc[i][j] = 0.f;

    const float* Ap = A + (size_t)(m0 + lr) * K + lk;
    const float* Bp = Bw + (size_t)(n0 + lr) * K + lk;

    for (int k0 = 0; k0 < K; k0 += 16) {
        float4 a0 = *(const float4*)(Ap + k0);
        float4 a1 = *(const float4*)(Ap + k0 + 4);
        float4 b0 = *(const float4*)(Bp + k0);
        float4 b1 = *(const float4*)(Bp + k0 + 4);
        As[lk + 0][lr] = a0.x; As[lk + 1][lr] = a0.y; As[lk + 2][lr] = a0.z; As[lk + 3][lr] = a0.w;
        As[lk + 4][lr] = a1.x; As[lk + 5][lr] = a1.y; As[lk + 6][lr] = a1.z; As[lk + 7][lr] = a1.w;
        Bs[lk + 0][lr] = b0.x; Bs[lk + 1][lr] = b0.y; Bs[lk + 2][lr] = b0.z; Bs[lk + 3][lr] = b0.w;
        Bs[lk + 4][lr] = b1.x; Bs[lk + 5][lr] = b1.y; Bs[lk + 6][lr] = b1.z; Bs[lk + 7][lr] = b1.w;
        __syncthreads();
#pragma unroll
        for (int kk = 0; kk < 16; kk++) {
            float4 aA = *(const float4*)&As[kk][ty * 8];
            float4 aB = *(const float4*)&As[kk][ty * 8 + 4];
            float4 bA = *(const float4*)&Bs[kk][tx * 8];
            float4 bB = *(const float4*)&Bs[kk][tx * 8 + 4];
            float ar[8] = {aA.x, aA.y, aA.z, aA.w, aB.x, aB.y, aB.z, aB.w};
            float br[8] = {bA.x, bA.y, bA.z, bA.w, bB.x, bB.y, bB.z, bB.w};
#pragma unroll
            for (int i = 0; i < 8; i++)
#pragma unroll
                for (int j = 0; j < 8; j++) acc[i][j] += ar[i] * br[j];
        }
        __syncthreads();
    }

#pragma unroll
    for (int i = 0; i < 8; i++) {
        int m = m0 + ty * 8 + i;
#pragma unroll
        for (int j = 0; j < 8; j++) {
            int n = n0 + tx * 8 + j;
            if (EPI == 0) {
                C[(size_t)m * N + n] = acc[i][j];
            } else {
                int b = m >> 12;          // S = 4096
                int s = m & (SS - 1);
                int h = n >> 6;           // D = 64
                int d = n & 63;
                C[(((size_t)(b * NHH + h) * SS + s) * DD) + d] = acc[i][j];
            }
        }
    }
}

// ---------------- RoPE (in-place on q and k, (b,h,s,d) layout) ----------------
__global__ void rope_kernel(float* __restrict__ q, float* __restrict__ k,
                            const float* __restrict__ cosT, const float* __restrict__ sinT) {
    int idx = blockIdx.x * blockDim.x + threadIdx.x;
    if (idx >= BB * NHH * SS * 32) return;
    int d = idx & 31;
    int bhs = idx >> 5;
    int s = bhs & (SS - 1);
    size_t base = (size_t)bhs * DD;
    float c1 = cosT[s * DD + d],      s1 = sinT[s * DD + d];
    float c2 = cosT[s * DD + d + 32], s2 = sinT[s * DD + d + 32];
    float x1 = q[base + d], x2 = q[base + d + 32];
    q[base + d]      = x1 * c1 - x2 * s1;
    q[base + d + 32] = x2 * c2 + x1 * s2;
    x1 = k[base + d]; x2 = k[base + d + 32];
    k[base + d]      = x1 * c1 - x2 * s1;
    k[base + d + 32] = x2 * c2 + x1 * s2;
}

// ---------------- per-chunk RFA summaries ----------------
__global__ void __launch_bounds__(128) rfa_kernel(const float* __restrict__ k,
                                                  const float* __restrict__ v,
                                                  const float* __restrict__ mu,
                                                  const float* __restrict__ phi,
                                                  float* __restrict__ rk,
                                                  float* __restrict__ rv) {
    int bh = blockIdx.x / NCC;
    int c  = blockIdx.x % NCC;
    int h  = bh % NHH;
    int j  = threadIdx.x;
    __shared__ float sb[CHUNKK], sg[CHUNKK];
    const float* kbase = k + ((size_t)bh * SS + c * CHUNKK) * DD;
    const float* vbase = v + ((size_t)bh * SS + c * CHUNKK) * DD;
    const float* kr = kbase + j * DD;
    float dm = 0.f, dp = 0.f, nn = 0.f;
#pragma unroll
    for (int d = 0; d < DD; d++) {
        float kv = kr[d];
        dm += kv * mu[h * DD + d];
        dp += kv * phi[h * DD + d];
        nn += kv * kv;
    }
    float halfn = 0.5f * SCALEF * nn;
    sb[j] = SCALEF * dm - halfn;
    sg[j] = SCALEF * dp - halfn;
    __syncthreads();
    float mb = -1e30f, mg = -1e30f;
    for (int t = 0; t < CHUNKK; t++) { mb = fmaxf(mb, sb[t]); mg = fmaxf(mg, sg[t]); }
    float eb = expf(sb[j] - mb), eg = expf(sg[j] - mg);
    __syncthreads();
    sb[j] = eb; sg[j] = eg;
    __syncthreads();
    float zb = 0.f, zg = 0.f;
    for (int t = 0; t < CHUNKK; t++) { zb += sb[t]; zg += sg[t]; }
    float invb = 1.f / zb, invg = 1.f / zg;
    if (j < DD) {
        int d = j;
        float acc = 0.f;
        for (int t = 0; t < CHUNKK; t++) acc += sb[t] * kbase[t * DD + d];
        rk[((size_t)bh * NCC + c) * DD + d] = acc * invb;
    } else {
        int d = j - DD;
        float acc = 0.f;
        for (int t = 0; t < CHUNKK; t++) acc += sg[t] * vbase[t * DD + d];
        rv[((size_t)bh * NCC + c) * DD + d] = acc * invg;
    }
}

// ---------------- windowed attention + chunk RFA, joint online softmax ----------------
__global__ void __launch_bounds__(128) attn_kernel(const float* __restrict__ q,
                                                   const float* __restrict__ k,
                                                   const float* __restrict__ v,
                                                   const float* __restrict__ rk,
                                                   const float* __restrict__ rv,
                                                   float* __restrict__ out) {
    __shared__ __align__(16) float Ks[32][64];
    __shared__ __align__(16) float Vs[32][64];
    const int rt  = blockIdx.x;           // query tile within window (0..3)
    const int w   = blockIdx.y;           // window 0..7
    const int bh  = blockIdx.z;           // b*NH + h
    const int b   = bh / NHH, h = bh % NHH;
    const int tid = threadIdx.x;
    const int i   = rt * 128 + tid;       // query index within window

    const float* qrow = q + ((size_t)bh * SS + w * WINN + i) * DD;
    float qr[64];
#pragma unroll
    for (int d = 0; d < 64; d++) qr[d] = qrow[d] * SCALEF;
    float acc[64];
#pragma unroll
    for (int d = 0; d < 64; d++) acc[d] = 0.f;
    float m = -1e30f, l = 0.f;

    const float* kwin = k + ((size_t)bh * SS + w * WINN) * DD;
    const float* vwin = v + ((size_t)bh * SS + w * WINN) * DD;

    // --- causal window part: tiles of 32 keys covering keys [0, rt*128+128) ---
    const int ntiles = rt * 4 + 4;
    for (int kt = 0; kt < ntiles; kt++) {
        int kt0 = kt * 32;
        const float4* ksrc = (const float4*)(kwin + (size_t)kt0 * 64);
        const float4* vsrc = (const float4*)(vwin + (size_t)kt0 * 64);
        float4* kdst = (float4*)&Ks[0][0];
        float4* vdst = (float4*)&Vs[0][0];
#pragma unroll
        for (int t = 0; t < 4; t++) {
            kdst[tid + t * 128] = ksrc[tid + t * 128];
            vdst[tid + t * 128] = vsrc[tid + t * 128];
        }
        __syncthreads();
        float sc[32];
        float tmax = -1e30f;
#pragma unroll
        for (int jj = 0; jj < 32; jj++) {
            float sdot = 0.f;
#pragma unroll
            for (int d = 0; d < 64; d++) sdot += qr[d] * Ks[jj][d];
            sdot = (kt0 + jj <= i) ? sdot : -1e30f;
            sc[jj] = sdot;
            tmax = fmaxf(tmax, sdot);
        }
        if (tmax > -1e29f) {
            float mnew = fmaxf(m, tmax);
            float f = __expf(m - mnew);
            l *= f;
#pragma unroll
            for (int d = 0; d < 64; d++) acc[d] *= f;
#pragma unroll
            for (int jj = 0; jj < 32; jj++) {
                float p = __expf(sc[jj] - mnew);
                l += p;
#pragma unroll
                for (int d = 0; d < 64; d++) acc[d] += p * Vs[jj][d];
            }
            m = mnew;
        }
        __syncthreads();
    }

    // --- chunk-RFA part: chunks c < 4*w (summaries of strictly earlier windows) ---
    const int nch = 4 * w;
    for (int ct0 = 0; ct0 < nch; ct0 += 32) {
        int cnt = min(32, nch - ct0);
        const float4* ksrc = (const float4*)(rk + ((size_t)bh * NCC + ct0) * DD);
        const float4* vsrc = (const float4*)(rv + ((size_t)bh * NCC + ct0) * DD);
        for (int t = tid; t < cnt * 16; t += 128) {
            ((float4*)&Ks[0][0])[t] = ksrc[t];
            ((float4*)&Vs[0][0])[t] = vsrc[t];
        }
        __syncthreads();
        float sc[32];
        float tmax = -1e30f;
#pragma unroll
        for (int jj = 0; jj < 32; jj++) {
            float sdot = -1e30f;
            if (jj < cnt) {
                sdot = 0.f;
#pragma unroll
                for (int d = 0; d < 64; d++) sdot += qr[d] * Ks[jj][d];
            }
            sc[jj] = sdot;
            tmax = fmaxf(tmax, sdot);
        }
        float mnew = fmaxf(m, tmax);
        float f = __expf(m - mnew);
        l *= f;
#pragma unroll
        for (int d = 0; d < 64; d++) acc[d] *= f;
#pragma unroll
        for (int jj = 0; jj < 32; jj++) {
            float p = __expf(sc[jj] - mnew);
            l += p;
#pragma unroll
            for (int d = 0; d < 64; d++) acc[d] += p * Vs[jj][d];
        }
        m = mnew;
        __syncthreads();
    }

    float inv = 1.f / l;
    float* orow = out + ((size_t)b * SS + w * WINN + i) * HIDD + h * DD;
#pragma unroll
    for (int d = 0; d < 64; d++) orow[d] = acc[d] * inv;
}

// ---------------- launch ----------------
extern "C" void kernel_launch(void* const* d_in, const int* in_sizes, int n_in,
                              void* d_out, int out_size) {
    const float* hidden = (const float*)d_in[0];
    const float* Wq     = (const float*)d_in[1];
    const float* Wk     = (const float*)d_in[2];
    const float* Wv     = (const float*)d_in[3];
    const float* Wo     = (const float*)d_in[4];
    const float* mu     = (const float*)d_in[5];
    const float* phi    = (const float*)d_in[6];
    const float* cosT   = (const float*)d_in[7];
    const float* sinT   = (const float*)d_in[8];

    float *qb, *kb, *vb, *ab, *rkb, *rvb;
    cudaGetSymbolAddress((void**)&qb,  g_q);
    cudaGetSymbolAddress((void**)&kb,  g_k);
    cudaGetSymbolAddress((void**)&vb,  g_v);
    cudaGetSymbolAddress((void**)&ab,  g_attn);
    cudaGetSymbolAddress((void**)&rkb, g_rfak);
    cudaGetSymbolAddress((void**)&rvb, g_rfav);

    dim3 ggrid(HIDD / 128, MTOK / 128);
    sgemm_nt<1><<<ggrid, 256>>>(hidden, Wq, qb, MTOK, HIDD, HIDD);
    sgemm_nt<1><<<ggrid, 256>>>(hidden, Wk, kb, MTOK, HIDD, HIDD);
    sgemm_nt<1><<<ggrid, 256>>>(hidden, Wv, vb, MTOK, HIDD, HIDD);

    rope_kernel<<<(BB * NHH * SS * 32) / 256, 256>>>(qb, kb, cosT, sinT);

    rfa_kernel<<<BB * NHH * NCC, 128>>>(kb, vb, mu, phi, rkb, rvb);

    attn_kernel<<<dim3(WINN / 128, NWW, BB * NHH), 128>>>(qb, kb, vb, rkb, rvb, ab);

    sgemm_nt<0><<<ggrid, 256>>>(ab, Wo, (float*)d_out, MTOK, HIDD, HIDD);
}

// round 3
// speedup vs baseline: 1.6279x; 1.6279x over previous
#include <cuda_runtime.h>
#include <cuda_bf16.h>
#include <cstdint>
#include <math.h>

// ---------------- problem constants ----------------
#define BB     4
#define SS     4096
#define HIDD   1024
#define NHH    16
#define DD     64
#define WINN   512
#define CHUNKK 128
#define NWW    8
#define NCC    32
#define SCALEF 0.125f
#define MTOK   (BB*SS)   // 16384
#define GK     1024
#define GN     1024

// ---------------- scratch (device globals) ----------------
__device__ float g_q[MTOK*HIDD];
__device__ float g_k[MTOK*HIDD];
__device__ float g_v[MTOK*HIDD];
__device__ float g_attn[MTOK*HIDD];
__device__ float g_rfak[BB*NHH*NCC*DD];
__device__ float g_rfav[BB*NHH*NCC*DD];

// ================= helpers =================
__device__ __forceinline__ uint32_t smem_u32(const void* p) {
    uint32_t a;
    asm("{ .reg .u64 t; cvta.to.shared.u64 t, %1; cvt.u32.u64 %0, t; }" : "=r"(a) : "l"(p));
    return a;
}

#define LDSM_X4(r, a)                                                          \
    asm volatile("ldmatrix.sync.aligned.m8n8.x4.shared.b16 {%0,%1,%2,%3}, [%4];" \
        : "=r"((r)[0]), "=r"((r)[1]), "=r"((r)[2]), "=r"((r)[3]) : "r"(a))

#define MMA16816(c, a, b0, b1)                                                 \
    asm volatile("mma.sync.aligned.m16n8k16.row.col.f32.bf16.bf16.f32 "        \
        "{%0,%1,%2,%3}, {%4,%5,%6,%7}, {%8,%9}, {%0,%1,%2,%3};"                \
        : "+f"((c)[0]), "+f"((c)[1]), "+f"((c)[2]), "+f"((c)[3])               \
        : "r"((a)[0]), "r"((a)[1]), "r"((a)[2]), "r"((a)[3]), "r"(b0), "r"(b1))

// smem tile layout: bf16 [128][40] (stride 40 elems = 80B, conflict-free for ldmatrix)
#define TILE_B   10240              // 128*40*2 bytes
#define BUF_B    40960              // Ahi|Alo|Bhi|Blo per buffer
#define SMEM_DYN (2 * BUF_B)        // 81920

__device__ __forceinline__ void cvtsts(float4 f, uint32_t dhi, uint32_t dlo) {
    __nv_bfloat162 h0, h1, l0, l1;
    h0.x = __float2bfloat16(f.x); h0.y = __float2bfloat16(f.y);
    h1.x = __float2bfloat16(f.z); h1.y = __float2bfloat16(f.w);
    l0.x = __float2bfloat16(f.x - __bfloat162float(h0.x));
    l0.y = __float2bfloat16(f.y - __bfloat162float(h0.y));
    l1.x = __float2bfloat16(f.z - __bfloat162float(h1.x));
    l1.y = __float2bfloat16(f.w - __bfloat162float(h1.y));
    asm volatile("st.shared.v2.b32 [%0], {%1, %2};"
                 :: "r"(dhi), "r"(*(uint32_t*)&h0), "r"(*(uint32_t*)&h1) : "memory");
    asm volatile("st.shared.v2.b32 [%0], {%1, %2};"
                 :: "r"(dlo), "r"(*(uint32_t*)&l0), "r"(*(uint32_t*)&l1) : "memory");
}

// ============ Split-bf16 mma.sync GEMM: C[M,N] = A[M,K] * B[N,K]^T ============
__global__ void __launch_bounds__(256)
gemm_bf16s(const float* __restrict__ A, const float* __restrict__ Bw, float* __restrict__ C) {
    extern __shared__ char dsm[];
    const uint32_t sbase = smem_u32(dsm);

    const int tid  = threadIdx.x;
    const int lane = tid & 31;
    const int wid  = tid >> 5;
    const int wm   = wid >> 2;      // 0..1 (rows of 64)
    const int wn   = wid & 3;       // 0..3 (cols of 32)
    const int m0   = blockIdx.y * 128;
    const int n0   = blockIdx.x * 128;

    // ldmatrix per-thread row/col offsets
    const int rowoff = ((lane >> 3) & 1) * 8 + (lane & 7);
    const int koff   = (lane >> 4) * 8;

    float acc[4][4][4];
#pragma unroll
    for (int i = 0; i < 4; i++)
#pragma unroll
        for (int j = 0; j < 4; j++)
#pragma unroll
            for (int r = 0; r < 4; r++) acc[i][j][r] = 0.f;

    // fill mapping: pass p (0..3): row = p*32 + tid/8, col4 = (tid&7)*4
    const int frow = tid >> 3;
    const int fcol = (tid & 7) * 4;
    const uint32_t soff = (uint32_t)frow * 80 + (uint32_t)(tid & 7) * 8; // bytes (row part added per pass)

    float4 pa[4], pb[4];
#pragma unroll
    for (int p = 0; p < 4; p++) {
        int row = p * 32 + frow;
        pa[p] = *(const float4*)(A  + (size_t)(m0 + row) * GK + fcol);
        pb[p] = *(const float4*)(Bw + (size_t)(n0 + row) * GK + fcol);
    }

    for (int kc = 0; kc < GK / 32; kc++) {
        const int buf = kc & 1;
        const uint32_t smA = sbase + buf * BUF_B;          // Ahi
        const uint32_t smB = smA + 2 * TILE_B;             // Bhi

        // store current chunk (hi/lo split)
#pragma unroll
        for (int p = 0; p < 4; p++) {
            uint32_t off = (uint32_t)p * 32 * 80 + soff;
            cvtsts(pa[p], smA + off, smA + TILE_B + off);
            cvtsts(pb[p], smB + off, smB + TILE_B + off);
        }
        __syncthreads();

        // prefetch next chunk
        if (kc + 1 < GK / 32) {
            int col = fcol + (kc + 1) * 32;
#pragma unroll
            for (int p = 0; p < 4; p++) {
                int row = p * 32 + frow;
                pa[p] = *(const float4*)(A  + (size_t)(m0 + row) * GK + col);
                pb[p] = *(const float4*)(Bw + (size_t)(n0 + row) * GK + col);
            }
        }

        // mma over 2 k16-steps, 3 split passes
#pragma unroll
        for (int ks = 0; ks < 2; ks++) {
            uint32_t af[4][4], bh[2][4], bl[2][4];
#pragma unroll
            for (int mf = 0; mf < 4; mf++) {
                uint32_t a = smA + ((uint32_t)(wm * 64 + mf * 16 + rowoff) * 40 + ks * 16 + koff) * 2;
                LDSM_X4(af[mf], a);
            }
#pragma unroll
            for (int nb = 0; nb < 2; nb++) {
                uint32_t b = smB + ((uint32_t)(wn * 32 + nb * 16 + rowoff) * 40 + ks * 16 + koff) * 2;
                LDSM_X4(bh[nb], b);
                LDSM_X4(bl[nb], b + TILE_B);
            }
#pragma unroll
            for (int mf = 0; mf < 4; mf++)
#pragma unroll
                for (int nf = 0; nf < 4; nf++) {
                    MMA16816(acc[mf][nf], af[mf], bh[nf >> 1][nf & 1], bh[nf >> 1][(nf & 1) + 2]);
                    MMA16816(acc[mf][nf], af[mf], bl[nf >> 1][nf & 1], bl[nf >> 1][(nf & 1) + 2]);
                }
            // reload A-lo into same frag regs, third pass
#pragma unroll
            for (int mf = 0; mf < 4; mf++) {
                uint32_t a = smA + TILE_B + ((uint32_t)(wm * 64 + mf * 16 + rowoff) * 40 + ks * 16 + koff) * 2;
                LDSM_X4(af[mf], a);
            }
#pragma unroll
            for (int mf = 0; mf < 4; mf++)
#pragma unroll
                for (int nf = 0; nf < 4; nf++)
                    MMA16816(acc[mf][nf], af[mf], bh[nf >> 1][nf & 1], bh[nf >> 1][(nf & 1) + 2]);
        }
        __syncthreads();
    }

    // epilogue: direct float2 stores
#pragma unroll
    for (int mf = 0; mf < 4; mf++) {
        int r0 = m0 + wm * 64 + mf * 16 + (lane >> 2);
#pragma unroll
        for (int nf = 0; nf < 4; nf++) {
            int c0 = n0 + wn * 32 + nf * 8 + (lane & 3) * 2;
            float2 v0 = make_float2(acc[mf][nf][0], acc[mf][nf][1]);
            float2 v1 = make_float2(acc[mf][nf][2], acc[mf][nf][3]);
            *(float2*)(C + (size_t)r0 * GN + c0)       = v0;
            *(float2*)(C + (size_t)(r0 + 8) * GN + c0) = v1;
        }
    }
}

// ================= RoPE ((b,s,h,d) layout) =================
__global__ void rope_kernel(float* __restrict__ q, float* __restrict__ k,
                            const float* __restrict__ cosT, const float* __restrict__ sinT) {
    int idx = blockIdx.x * blockDim.x + threadIdx.x;
    if (idx >= BB * SS * NHH * 32) return;
    int d = idx & 31;
    int r = idx >> 5;
    int s = (r >> 4) & (SS - 1);
    size_t base = (size_t)r * DD;
    float c1 = cosT[s * DD + d],      s1 = sinT[s * DD + d];
    float c2 = cosT[s * DD + d + 32], s2 = sinT[s * DD + d + 32];
    float x1 = q[base + d], x2 = q[base + d + 32];
    q[base + d]      = x1 * c1 - x2 * s1;
    q[base + d + 32] = x2 * c2 + x1 * s2;
    x1 = k[base + d]; x2 = k[base + d + 32];
    k[base + d]      = x1 * c1 - x2 * s1;
    k[base + d + 32] = x2 * c2 + x1 * s2;
}

// ================= per-chunk RFA summaries ((b,s,h,d)) =================
__global__ void __launch_bounds__(128) rfa_kernel(const float* __restrict__ k,
                                                  const float* __restrict__ v,
                                                  const float* __restrict__ mu,
                                                  const float* __restrict__ phi,
                                                  float* __restrict__ rk,
                                                  float* __restrict__ rv) {
    int bh = blockIdx.x / NCC;
    int c  = blockIdx.x % NCC;
    int b  = bh / NHH, h = bh % NHH;
    int j  = threadIdx.x;
    __shared__ float sb[CHUNKK], sg[CHUNKK];
    const float* kbase = k + (((size_t)b * SS + c * CHUNKK) * NHH + h) * DD;
    const float* vbase = v + (((size_t)b * SS + c * CHUNKK) * NHH + h) * DD;
    const float* kr = kbase + (size_t)j * HIDD;
    float dm = 0.f, dp = 0.f, nn = 0.f;
#pragma unroll
    for (int d = 0; d < DD; d++) {
        float kv = kr[d];
        dm += kv * mu[h * DD + d];
        dp += kv * phi[h * DD + d];
        nn += kv * kv;
    }
    float halfn = 0.5f * SCALEF * nn;
    sb[j] = SCALEF * dm - halfn;
    sg[j] = SCALEF * dp - halfn;
    __syncthreads();
    float mb = -1e30f, mg = -1e30f;
    for (int t = 0; t < CHUNKK; t++) { mb = fmaxf(mb, sb[t]); mg = fmaxf(mg, sg[t]); }
    float eb = expf(sb[j] - mb), eg = expf(sg[j] - mg);
    __syncthreads();
    sb[j] = eb; sg[j] = eg;
    __syncthreads();
    float zb = 0.f, zg = 0.f;
    for (int t = 0; t < CHUNKK; t++) { zb += sb[t]; zg += sg[t]; }
    float invb = 1.f / zb, invg = 1.f / zg;
    if (j < DD) {
        int d = j;
        float acc = 0.f;
        for (int t = 0; t < CHUNKK; t++) acc += sb[t] * kbase[(size_t)t * HIDD + d];
        rk[((size_t)bh * NCC + c) * DD + d] = acc * invb;
    } else {
        int d = j - DD;
        float acc = 0.f;
        for (int t = 0; t < CHUNKK; t++) acc += sg[t] * vbase[(size_t)t * HIDD + d];
        rv[((size_t)bh * NCC + c) * DD + d] = acc * invg;
    }
}

// ================= attention ((b,s,h,d) in, (b,s,hid) out) =================
__global__ void __launch_bounds__(128) attn_kernel(const float* __restrict__ q,
                                                   const float* __restrict__ k,
                                                   const float* __restrict__ v,
                                                   const float* __restrict__ rk,
                                                   const float* __restrict__ rv,
                                                   float* __restrict__ out) {
    __shared__ __align__(16) float Ks[32][64];
    __shared__ __align__(16) float Vs[32][64];
    const int rt  = blockIdx.x;
    const int w   = blockIdx.y;
    const int bh  = blockIdx.z;
    const int b   = bh / NHH, h = bh % NHH;
    const int tid = threadIdx.x;
    const int i   = rt * 128 + tid;

    const float* qrow = q + (((size_t)b * SS + w * WINN + i) * NHH + h) * DD;
    float qr[64];
#pragma unroll
    for (int d = 0; d < 64; d++) qr[d] = qrow[d] * SCALEF;
    float acc[64];
#pragma unroll
    for (int d = 0; d < 64; d++) acc[d] = 0.f;
    float m = -1e30f, l = 0.f;

    const float* kwin = k + (((size_t)b * SS + w * WINN) * NHH + h) * DD;
    const float* vwin = v + (((size_t)b * SS + w * WINN) * NHH + h) * DD;

    const int ntiles = rt * 4 + 4;
    for (int kt = 0; kt < ntiles; kt++) {
        int kt0 = kt * 32;
#pragma unroll
        for (int t = tid; t < 512; t += 128) {
            int rr = t >> 4, cc = t & 15;
            ((float4*)&Ks[rr][0])[cc] = ((const float4*)(kwin + (size_t)(kt0 + rr) * HIDD))[cc];
            ((float4*)&Vs[rr][0])[cc] = ((const float4*)(vwin + (size_t)(kt0 + rr) * HIDD))[cc];
        }
        __syncthreads();
        float sc[32];
        float tmax = -1e30f;
#pragma unroll
        for (int jj = 0; jj < 32; jj++) {
            float sdot = 0.f;
#pragma unroll
            for (int d = 0; d < 64; d++) sdot += qr[d] * Ks[jj][d];
            sdot = (kt0 + jj <= i) ? sdot : -1e30f;
            sc[jj] = sdot;
            tmax = fmaxf(tmax, sdot);
        }
        if (tmax > -1e29f) {
            float mnew = fmaxf(m, tmax);
            float f = __expf(m - mnew);
            l *= f;
#pragma unroll
            for (int d = 0; d < 64; d++) acc[d] *= f;
#pragma unroll
            for (int jj = 0; jj < 32; jj++) {
                float p = __expf(sc[jj] - mnew);
                l += p;
#pragma unroll
                for (int d = 0; d < 64; d++) acc[d] += p * Vs[jj][d];
            }
            m = mnew;
        }
        __syncthreads();
    }

    const int nch = 4 * w;
    for (int ct0 = 0; ct0 < nch; ct0 += 32) {
        int cnt = min(32, nch - ct0);
        const float4* ksrc = (const float4*)(rk + ((size_t)bh * NCC + ct0) * DD);
        const float4* vsrc = (const float4*)(rv + ((size_t)bh * NCC + ct0) * DD);
        for (int t = tid; t < cnt * 16; t += 128) {
            ((float4*)&Ks[0][0])[t] = ksrc[t];
            ((float4*)&Vs[0][0])[t] = vsrc[t];
        }
        __syncthreads();
        float sc[32];
        float tmax = -1e30f;
#pragma unroll
        for (int jj = 0; jj < 32; jj++) {
            float sdot = -1e30f;
            if (jj < cnt) {
                sdot = 0.f;
#pragma unroll
                for (int d = 0; d < 64; d++) sdot += qr[d] * Ks[jj][d];
            }
            sc[jj] = sdot;
            tmax = fmaxf(tmax, sdot);
        }
        float mnew = fmaxf(m, tmax);
        float f = __expf(m - mnew);
        l *= f;
#pragma unroll
        for (int d = 0; d < 64; d++) acc[d] *= f;
#pragma unroll
        for (int jj = 0; jj < 32; jj++) {
            float p = __expf(sc[jj] - mnew);
            l += p;
#pragma unroll
            for (int d = 0; d < 64; d++) acc[d] += p * Vs[jj][d];
        }
        m = mnew;
        __syncthreads();
    }

    float inv = 1.f / l;
    float* orow = out + ((size_t)b * SS + (size_t)w * WINN + i) * HIDD + h * DD;
#pragma unroll
    for (int d = 0; d < 64; d++) orow[d] = acc[d] * inv;
}

// ---------------- launch ----------------
extern "C" void kernel_launch(void* const* d_in, const int* in_sizes, int n_in,
                              void* d_out, int out_size) {
    const float* hidden = (const float*)d_in[0];
    const float* Wq     = (const float*)d_in[1];
    const float* Wk     = (const float*)d_in[2];
    const float* Wv     = (const float*)d_in[3];
    const float* Wo     = (const float*)d_in[4];
    const float* mu     = (const float*)d_in[5];
    const float* phi    = (const float*)d_in[6];
    const float* cosT   = (const float*)d_in[7];
    const float* sinT   = (const float*)d_in[8];

    float *qb, *kb, *vb, *ab, *rkb, *rvb;
    cudaGetSymbolAddress((void**)&qb,  g_q);
    cudaGetSymbolAddress((void**)&kb,  g_k);
    cudaGetSymbolAddress((void**)&vb,  g_v);
    cudaGetSymbolAddress((void**)&ab,  g_attn);
    cudaGetSymbolAddress((void**)&rkb, g_rfak);
    cudaGetSymbolAddress((void**)&rvb, g_rfav);

    static bool attr_set = false;
    if (!attr_set) {
        cudaFuncSetAttribute((const void*)gemm_bf16s,
                             cudaFuncAttributeMaxDynamicSharedMemorySize, SMEM_DYN);
        attr_set = true;
    }

    dim3 ggrid(GN / 128, MTOK / 128);
    gemm_bf16s<<<ggrid, 256, SMEM_DYN>>>(hidden, Wq, qb);
    gemm_bf16s<<<ggrid, 256, SMEM_DYN>>>(hidden, Wk, kb);
    gemm_bf16s<<<ggrid, 256, SMEM_DYN>>>(hidden, Wv, vb);

    rope_kernel<<<(BB * SS * NHH * 32) / 256, 256>>>(qb, kb, cosT, sinT);

    rfa_kernel<<<BB * NHH * NCC, 128>>>(kb, vb, mu, phi, rkb, rvb);

    attn_kernel<<<dim3(WINN / 128, NWW, BB * NHH), 128>>>(qb, kb, vb, rkb, rvb, ab);

    gemm_bf16s<<<ggrid, 256, SMEM_DYN>>>(ab, Wo, (float*)d_out);
}

// round 5
// speedup vs baseline: 1.6284x; 1.0003x over previous
#include <cuda_runtime.h>
#include <cuda_bf16.h>
#include <cstdint>
#include <math.h>

// ---------------- problem constants ----------------
#define BB     4
#define SS     4096
#define HIDD   1024
#define NHH    16
#define DD     64
#define WINN   512
#define CHUNKK 128
#define NWW    8
#define NCC    32
#define SCALEF 0.125f
#define MTOK   (BB*SS)   // 16384
#define GK     1024
#define GN     1024

// ---------------- scratch (device globals) ----------------
__device__ float g_q[MTOK*HIDD];
__device__ float g_k[MTOK*HIDD];
__device__ float g_v[MTOK*HIDD];
__device__ float g_attn[MTOK*HIDD];
__device__ float g_rfak[BB*NHH*NCC*DD];
__device__ float g_rfav[BB*NHH*NCC*DD];

// ================= helpers =================
__device__ __forceinline__ uint32_t smem_u32(const void* p) {
    uint32_t a;
    asm("{ .reg .u64 t; cvta.to.shared.u64 t, %1; cvt.u32.u64 %0, t; }" : "=r"(a) : "l"(p));
    return a;
}

#define LDSM_X4(r, a)                                                          \
    asm volatile("ldmatrix.sync.aligned.m8n8.x4.shared.b16 {%0,%1,%2,%3}, [%4];" \
        : "=r"((r)[0]), "=r"((r)[1]), "=r"((r)[2]), "=r"((r)[3]) : "r"(a))

#define MMA16816(c, a, b0, b1)                                                 \
    asm volatile("mma.sync.aligned.m16n8k16.row.col.f32.bf16.bf16.f32 "        \
        "{%0,%1,%2,%3}, {%4,%5,%6,%7}, {%8,%9}, {%0,%1,%2,%3};"                \
        : "+f"((c)[0]), "+f"((c)[1]), "+f"((c)[2]), "+f"((c)[3])               \
        : "r"((a)[0]), "r"((a)[1]), "r"((a)[2]), "r"((a)[3]), "r"(b0), "r"(b1))

// smem tile layout: bf16 [128][40] (stride 40 elems = 80B, conflict-free for ldmatrix)
#define TILE_B   10240              // 128*40*2 bytes
#define BUF_B    40960              // Ahi|Alo|Bhi|Blo per buffer
#define SMEM_DYN (2 * BUF_B)        // 81920

__device__ __forceinline__ void cvtsts(float4 f, uint32_t dhi, uint32_t dlo) {
    __nv_bfloat162 h0, h1, l0, l1;
    h0.x = __float2bfloat16(f.x); h0.y = __float2bfloat16(f.y);
    h1.x = __float2bfloat16(f.z); h1.y = __float2bfloat16(f.w);
    l0.x = __float2bfloat16(f.x - __bfloat162float(h0.x));
    l0.y = __float2bfloat16(f.y - __bfloat162float(h0.y));
    l1.x = __float2bfloat16(f.z - __bfloat162float(h1.x));
    l1.y = __float2bfloat16(f.w - __bfloat162float(h1.y));
    asm volatile("st.shared.v2.b32 [%0], {%1, %2};"
                 :: "r"(dhi), "r"(*(uint32_t*)&h0), "r"(*(uint32_t*)&h1) : "memory");
    asm volatile("st.shared.v2.b32 [%0], {%1, %2};"
                 :: "r"(dlo), "r"(*(uint32_t*)&l0), "r"(*(uint32_t*)&l1) : "memory");
}

// ============ Split-bf16 mma.sync GEMM: C[M,N] = A[M,K] * B[N,K]^T ============
__global__ void __launch_bounds__(256)
gemm_bf16s(const float* __restrict__ A, const float* __restrict__ Bw, float* __restrict__ C) {
    extern __shared__ char dsm[];
    const uint32_t sbase = smem_u32(dsm);

    const int tid  = threadIdx.x;
    const int lane = tid & 31;
    const int wid  = tid >> 5;
    const int wm   = wid >> 2;      // 0..1 (rows of 64)
    const int wn   = wid & 3;       // 0..3 (cols of 32)
    const int m0   = blockIdx.y * 128;
    const int n0   = blockIdx.x * 128;

    // ldmatrix per-thread row/col offsets
    const int rowoff = ((lane >> 3) & 1) * 8 + (lane & 7);
    const int koff   = (lane >> 4) * 8;

    float acc[4][4][4];
#pragma unroll
    for (int i = 0; i < 4; i++)
#pragma unroll
        for (int j = 0; j < 4; j++)
#pragma unroll
            for (int r = 0; r < 4; r++) acc[i][j][r] = 0.f;

    // fill mapping: pass p (0..3): row = p*32 + tid/8, col4 = (tid&7)*4
    const int frow = tid >> 3;
    const int fcol = (tid & 7) * 4;
    const uint32_t soff = (uint32_t)frow * 80 + (uint32_t)(tid & 7) * 8; // bytes (row part added per pass)

    float4 pa[4], pb[4];
#pragma unroll
    for (int p = 0; p < 4; p++) {
        int row = p * 32 + frow;
        pa[p] = *(const float4*)(A  + (size_t)(m0 + row) * GK + fcol);
        pb[p] = *(const float4*)(Bw + (size_t)(n0 + row) * GK + fcol);
    }

    for (int kc = 0; kc < GK / 32; kc++) {
        const int buf = kc & 1;
        const uint32_t smA = sbase + buf * BUF_B;          // Ahi
        const uint32_t smB = smA + 2 * TILE_B;             // Bhi

        // store current chunk (hi/lo split)
#pragma unroll
        for (int p = 0; p < 4; p++) {
            uint32_t off = (uint32_t)p * 32 * 80 + soff;
            cvtsts(pa[p], smA + off, smA + TILE_B + off);
            cvtsts(pb[p], smB + off, smB + TILE_B + off);
        }
        __syncthreads();

        // prefetch next chunk
        if (kc + 1 < GK / 32) {
            int col = fcol + (kc + 1) * 32;
#pragma unroll
            for (int p = 0; p < 4; p++) {
                int row = p * 32 + frow;
                pa[p] = *(const float4*)(A  + (size_t)(m0 + row) * GK + col);
                pb[p] = *(const float4*)(Bw + (size_t)(n0 + row) * GK + col);
            }
        }

        // mma over 2 k16-steps, 3 split passes
#pragma unroll
        for (int ks = 0; ks < 2; ks++) {
            uint32_t af[4][4], bh[2][4], bl[2][4];
#pragma unroll
            for (int mf = 0; mf < 4; mf++) {
                uint32_t a = smA + ((uint32_t)(wm * 64 + mf * 16 + rowoff) * 40 + ks * 16 + koff) * 2;
                LDSM_X4(af[mf], a);
            }
#pragma unroll
            for (int nb = 0; nb < 2; nb++) {
                uint32_t b = smB + ((uint32_t)(wn * 32 + nb * 16 + rowoff) * 40 + ks * 16 + koff) * 2;
                LDSM_X4(bh[nb], b);
                LDSM_X4(bl[nb], b + TILE_B);
            }
#pragma unroll
            for (int mf = 0; mf < 4; mf++)
#pragma unroll
                for (int nf = 0; nf < 4; nf++) {
                    MMA16816(acc[mf][nf], af[mf], bh[nf >> 1][nf & 1], bh[nf >> 1][(nf & 1) + 2]);
                    MMA16816(acc[mf][nf], af[mf], bl[nf >> 1][nf & 1], bl[nf >> 1][(nf & 1) + 2]);
                }
            // reload A-lo into same frag regs, third pass
#pragma unroll
            for (int mf = 0; mf < 4; mf++) {
                uint32_t a = smA + TILE_B + ((uint32_t)(wm * 64 + mf * 16 + rowoff) * 40 + ks * 16 + koff) * 2;
                LDSM_X4(af[mf], a);
            }
#pragma unroll
            for (int mf = 0; mf < 4; mf++)
#pragma unroll
                for (int nf = 0; nf < 4; nf++)
                    MMA16816(acc[mf][nf], af[mf], bh[nf >> 1][nf & 1], bh[nf >> 1][(nf & 1) + 2]);
        }
        __syncthreads();
    }

    // epilogue: direct float2 stores
#pragma unroll
    for (int mf = 0; mf < 4; mf++) {
        int r0 = m0 + wm * 64 + mf * 16 + (lane >> 2);
#pragma unroll
        for (int nf = 0; nf < 4; nf++) {
            int c0 = n0 + wn * 32 + nf * 8 + (lane & 3) * 2;
            float2 v0 = make_float2(acc[mf][nf][0], acc[mf][nf][1]);
            float2 v1 = make_float2(acc[mf][nf][2], acc[mf][nf][3]);
            *(float2*)(C + (size_t)r0 * GN + c0)       = v0;
            *(float2*)(C + (size_t)(r0 + 8) * GN + c0) = v1;
        }
    }
}

// ================= RoPE ((b,s,h,d) layout) =================
__global__ void rope_kernel(float* __restrict__ q, float* __restrict__ k,
                            const float* __restrict__ cosT, const float* __restrict__ sinT) {
    int idx = blockIdx.x * blockDim.x + threadIdx.x;
    if (idx >= BB * SS * NHH * 32) return;
    int d = idx & 31;
    int r = idx >> 5;
    int s = (r >> 4) & (SS - 1);
    size_t base = (size_t)r * DD;
    float c1 = cosT[s * DD + d],      s1 = sinT[s * DD + d];
    float c2 = cosT[s * DD + d + 32], s2 = sinT[s * DD + d + 32];
    float x1 = q[base + d], x2 = q[base + d + 32];
    q[base + d]      = x1 * c1 - x2 * s1;
    q[base + d + 32] = x2 * c2 + x1 * s2;
    x1 = k[base + d]; x2 = k[base + d + 32];
    k[base + d]      = x1 * c1 - x2 * s1;
    k[base + d + 32] = x2 * c2 + x1 * s2;
}

// ================= per-chunk RFA summaries ((b,s,h,d)) =================
__global__ void __launch_bounds__(128) rfa_kernel(const float* __restrict__ k,
                                                  const float* __restrict__ v,
                                                  const float* __restrict__ mu,
                                                  const float* __restrict__ phi,
                                                  float* __restrict__ rk,
                                                  float* __restrict__ rv) {
    int bh = blockIdx.x / NCC;
    int c  = blockIdx.x % NCC;
    int b  = bh / NHH, h = bh % NHH;
    int j  = threadIdx.x;
    __shared__ float sb[CHUNKK], sg[CHUNKK];
    const float* kbase = k + (((size_t)b * SS + c * CHUNKK) * NHH + h) * DD;
    const float* vbase = v + (((size_t)b * SS + c * CHUNKK) * NHH + h) * DD;
    const float* kr = kbase + (size_t)j * HIDD;
    float dm = 0.f, dp = 0.f, nn = 0.f;
#pragma unroll
    for (int d = 0; d < DD; d++) {
        float kv = kr[d];
        dm += kv * mu[h * DD + d];
        dp += kv * phi[h * DD + d];
        nn += kv * kv;
    }
    float halfn = 0.5f * SCALEF * nn;
    sb[j] = SCALEF * dm - halfn;
    sg[j] = SCALEF * dp - halfn;
    __syncthreads();
    float mb = -1e30f, mg = -1e30f;
    for (int t = 0; t < CHUNKK; t++) { mb = fmaxf(mb, sb[t]); mg = fmaxf(mg, sg[t]); }
    float eb = expf(sb[j] - mb), eg = expf(sg[j] - mg);
    __syncthreads();
    sb[j] = eb; sg[j] = eg;
    __syncthreads();
    float zb = 0.f, zg = 0.f;
    for (int t = 0; t < CHUNKK; t++) { zb += sb[t]; zg += sg[t]; }
    float invb = 1.f / zb, invg = 1.f / zg;
    if (j < DD) {
        int d = j;
        float acc = 0.f;
        for (int t = 0; t < CHUNKK; t++) acc += sb[t] * kbase[(size_t)t * HIDD + d];
        rk[((size_t)bh * NCC + c) * DD + d] = acc * invb;
    } else {
        int d = j - DD;
        float acc = 0.f;
        for (int t = 0; t < CHUNKK; t++) acc += sg[t] * vbase[(size_t)t * HIDD + d];
        rv[((size_t)bh * NCC + c) * DD + d] = acc * invg;
    }
}

// ================= attention ((b,s,h,d) in, (b,s,hid) out) =================
__global__ void __launch_bounds__(128) attn_kernel(const float* __restrict__ q,
                                                   const float* __restrict__ k,
                                                   const float* __restrict__ v,
                                                   const float* __restrict__ rk,
                                                   const float* __restrict__ rv,
                                                   float* __restrict__ out) {
    __shared__ __align__(16) float Ks[32][64];
    __shared__ __align__(16) float Vs[32][64];
    const int rt  = blockIdx.x;
    const int w   = blockIdx.y;
    const int bh  = blockIdx.z;
    const int b   = bh / NHH, h = bh % NHH;
    const int tid = threadIdx.x;
    const int i   = rt * 128 + tid;

    const float* qrow = q + (((size_t)b * SS + w * WINN + i) * NHH + h) * DD;
    float qr[64];
#pragma unroll
    for (int d = 0; d < 64; d++) qr[d] = qrow[d] * SCALEF;
    float acc[64];
#pragma unroll
    for (int d = 0; d < 64; d++) acc[d] = 0.f;
    float m = -1e30f, l = 0.f;

    const float* kwin = k + (((size_t)b * SS + w * WINN) * NHH + h) * DD;
    const float* vwin = v + (((size_t)b * SS + w * WINN) * NHH + h) * DD;

    const int ntiles = rt * 4 + 4;
    for (int kt = 0; kt < ntiles; kt++) {
        int kt0 = kt * 32;
#pragma unroll
        for (int t = tid; t < 512; t += 128) {
            int rr = t >> 4, cc = t & 15;
            ((float4*)&Ks[rr][0])[cc] = ((const float4*)(kwin + (size_t)(kt0 + rr) * HIDD))[cc];
            ((float4*)&Vs[rr][0])[cc] = ((const float4*)(vwin + (size_t)(kt0 + rr) * HIDD))[cc];
        }
        __syncthreads();
        float sc[32];
        float tmax = -1e30f;
#pragma unroll
        for (int jj = 0; jj < 32; jj++) {
            float sdot = 0.f;
#pragma unroll
            for (int d = 0; d < 64; d++) sdot += qr[d] * Ks[jj][d];
            sdot = (kt0 + jj <= i) ? sdot : -1e30f;
            sc[jj] = sdot;
            tmax = fmaxf(tmax, sdot);
        }
        if (tmax > -1e29f) {
            float mnew = fmaxf(m, tmax);
            float f = __expf(m - mnew);
            l *= f;
#pragma unroll
            for (int d = 0; d < 64; d++) acc[d] *= f;
#pragma unroll
            for (int jj = 0; jj < 32; jj++) {
                float p = __expf(sc[jj] - mnew);
                l += p;
#pragma unroll
                for (int d = 0; d < 64; d++) acc[d] += p * Vs[jj][d];
            }
            m = mnew;
        }
        __syncthreads();
    }

    const int nch = 4 * w;
    for (int ct0 = 0; ct0 < nch; ct0 += 32) {
        int cnt = min(32, nch - ct0);
        const float4* ksrc = (const float4*)(rk + ((size_t)bh * NCC + ct0) * DD);
        const float4* vsrc = (const float4*)(rv + ((size_t)bh * NCC + ct0) * DD);
        for (int t = tid; t < cnt * 16; t += 128) {
            ((float4*)&Ks[0][0])[t] = ksrc[t];
            ((float4*)&Vs[0][0])[t] = vsrc[t];
        }
        __syncthreads();
        float sc[32];
        float tmax = -1e30f;
#pragma unroll
        for (int jj = 0; jj < 32; jj++) {
            float sdot = -1e30f;
            if (jj < cnt) {
                sdot = 0.f;
#pragma unroll
                for (int d = 0; d < 64; d++) sdot += qr[d] * Ks[jj][d];
            }
            sc[jj] = sdot;
            tmax = fmaxf(tmax, sdot);
        }
        float mnew = fmaxf(m, tmax);
        float f = __expf(m - mnew);
        l *= f;
#pragma unroll
        for (int d = 0; d < 64; d++) acc[d] *= f;
#pragma unroll
        for (int jj = 0; jj < 32; jj++) {
            float p = __expf(sc[jj] - mnew);
            l += p;
#pragma unroll
            for (int d = 0; d < 64; d++) acc[d] += p * Vs[jj][d];
        }
        m = mnew;
        __syncthreads();
    }

    float inv = 1.f / l;
    float* orow = out + ((size_t)b * SS + (size_t)w * WINN + i) * HIDD + h * DD;
#pragma unroll
    for (int d = 0; d < 64; d++) orow[d] = acc[d] * inv;
}

// ---------------- launch ----------------
extern "C" void kernel_launch(void* const* d_in, const int* in_sizes, int n_in,
                              void* d_out, int out_size) {
    const float* hidden = (const float*)d_in[0];
    const float* Wq     = (const float*)d_in[1];
    const float* Wk     = (const float*)d_in[2];
    const float* Wv     = (const float*)d_in[3];
    const float* Wo     = (const float*)d_in[4];
    const float* mu     = (const float*)d_in[5];
    const float* phi    = (const float*)d_in[6];
    const float* cosT   = (const float*)d_in[7];
    const float* sinT   = (const float*)d_in[8];

    float *qb, *kb, *vb, *ab, *rkb, *rvb;
    cudaGetSymbolAddress((void**)&qb,  g_q);
    cudaGetSymbolAddress((void**)&kb,  g_k);
    cudaGetSymbolAddress((void**)&vb,  g_v);
    cudaGetSymbolAddress((void**)&ab,  g_attn);
    cudaGetSymbolAddress((void**)&rkb, g_rfak);
    cudaGetSymbolAddress((void**)&rvb, g_rfav);

    static bool attr_set = false;
    if (!attr_set) {
        cudaFuncSetAttribute((const void*)gemm_bf16s,
                             cudaFuncAttributeMaxDynamicSharedMemorySize, SMEM_DYN);
        attr_set = true;
    }

    dim3 ggrid(GN / 128, MTOK / 128);
    gemm_bf16s<<<ggrid, 256, SMEM_DYN>>>(hidden, Wq, qb);
    gemm_bf16s<<<ggrid, 256, SMEM_DYN>>>(hidden, Wk, kb);
    gemm_bf16s<<<ggrid, 256, SMEM_DYN>>>(hidden, Wv, vb);

    rope_kernel<<<(BB * SS * NHH * 32) / 256, 256>>>(qb, kb, cosT, sinT);

    rfa_kernel<<<BB * NHH * NCC, 128>>>(kb, vb, mu, phi, rkb, rvb);

    attn_kernel<<<dim3(WINN / 128, NWW, BB * NHH), 128>>>(qb, kb, vb, rkb, rvb, ab);

    gemm_bf16s<<<ggrid, 256, SMEM_DYN>>>(ab, Wo, (float*)d_out);
}

// round 6
// speedup vs baseline: 2.5737x; 1.5805x over previous
#include <cuda_runtime.h>
#include <cuda_bf16.h>
#include <cstdint>
#include <math.h>

// ---------------- problem constants ----------------
#define BB     4
#define SS     4096
#define HIDD   1024
#define NHH    16
#define DD     64
#define WINN   512
#define CHUNKK 128
#define NWW    8
#define NCC    32
#define SCALEF 0.125f
#define MTOK   (BB*SS)   // 16384
#define GK     1024
#define GN     1024

// ---------------- scratch (device globals) ----------------
__device__ float g_q[MTOK*HIDD];
__device__ float g_k[MTOK*HIDD];
__device__ float g_v[MTOK*HIDD];
__device__ float g_attn[MTOK*HIDD];
__device__ float g_rfak[BB*NHH*NCC*DD];
__device__ float g_rfav[BB*NHH*NCC*DD];

// ================= helpers =================
__device__ __forceinline__ uint32_t smem_u32(const void* p) {
    uint32_t a;
    asm("{ .reg .u64 t; cvta.to.shared.u64 t, %1; cvt.u32.u64 %0, t; }" : "=r"(a) : "l"(p));
    return a;
}

#define LDSM_X4(r, a)                                                          \
    asm volatile("ldmatrix.sync.aligned.m8n8.x4.shared.b16 {%0,%1,%2,%3}, [%4];" \
        : "=r"((r)[0]), "=r"((r)[1]), "=r"((r)[2]), "=r"((r)[3]) : "r"(a))

#define LDSM_X4T(r, a)                                                         \
    asm volatile("ldmatrix.sync.aligned.m8n8.x4.trans.shared.b16 {%0,%1,%2,%3}, [%4];" \
        : "=r"((r)[0]), "=r"((r)[1]), "=r"((r)[2]), "=r"((r)[3]) : "r"(a))

#define MMA16816(c, a, b0, b1)                                                 \
    asm volatile("mma.sync.aligned.m16n8k16.row.col.f32.bf16.bf16.f32 "        \
        "{%0,%1,%2,%3}, {%4,%5,%6,%7}, {%8,%9}, {%0,%1,%2,%3};"                \
        : "+f"((c)[0]), "+f"((c)[1]), "+f"((c)[2]), "+f"((c)[3])               \
        : "r"((a)[0]), "r"((a)[1]), "r"((a)[2]), "r"((a)[3]), "r"(b0), "r"(b1))

#define MMA16816R(c, a0, a1, a2, a3, b0, b1)                                   \
    asm volatile("mma.sync.aligned.m16n8k16.row.col.f32.bf16.bf16.f32 "        \
        "{%0,%1,%2,%3}, {%4,%5,%6,%7}, {%8,%9}, {%0,%1,%2,%3};"                \
        : "+f"((c)[0]), "+f"((c)[1]), "+f"((c)[2]), "+f"((c)[3])               \
        : "r"(a0), "r"(a1), "r"(a2), "r"(a3), "r"(b0), "r"(b1))

__device__ __forceinline__ void cvtsts(float4 f, uint32_t dhi, uint32_t dlo) {
    __nv_bfloat162 h0, h1, l0, l1;
    h0.x = __float2bfloat16(f.x); h0.y = __float2bfloat16(f.y);
    h1.x = __float2bfloat16(f.z); h1.y = __float2bfloat16(f.w);
    l0.x = __float2bfloat16(f.x - __bfloat162float(h0.x));
    l0.y = __float2bfloat16(f.y - __bfloat162float(h0.y));
    l1.x = __float2bfloat16(f.z - __bfloat162float(h1.x));
    l1.y = __float2bfloat16(f.w - __bfloat162float(h1.y));
    asm volatile("st.shared.v2.b32 [%0], {%1, %2};"
                 :: "r"(dhi), "r"(*(uint32_t*)&h0), "r"(*(uint32_t*)&h1) : "memory");
    asm volatile("st.shared.v2.b32 [%0], {%1, %2};"
                 :: "r"(dlo), "r"(*(uint32_t*)&l0), "r"(*(uint32_t*)&l1) : "memory");
}

__device__ __forceinline__ void packsplit(float x, float y, uint32_t& hi, uint32_t& lo) {
    __nv_bfloat162 h, l;
    h.x = __float2bfloat16(x); h.y = __float2bfloat16(y);
    l.x = __float2bfloat16(x - __bfloat162float(h.x));
    l.y = __float2bfloat16(y - __bfloat162float(h.y));
    hi = *(uint32_t*)&h; lo = *(uint32_t*)&l;
}

// ============ Split-bf16 mma.sync GEMM: C[M,N] = A[M,K] * B[N,K]^T ============
#define TILE_B   10240
#define BUF_B    40960
#define SMEM_DYN (2 * BUF_B)

__global__ void __launch_bounds__(256)
gemm_bf16s(const float* __restrict__ A, const float* __restrict__ Bw, float* __restrict__ C) {
    extern __shared__ char dsm[];
    const uint32_t sbase = smem_u32(dsm);

    const int tid  = threadIdx.x;
    const int lane = tid & 31;
    const int wid  = tid >> 5;
    const int wm   = wid >> 2;
    const int wn   = wid & 3;
    const int m0   = blockIdx.y * 128;
    const int n0   = blockIdx.x * 128;

    const int rowoff = ((lane >> 3) & 1) * 8 + (lane & 7);
    const int koff   = (lane >> 4) * 8;

    float acc[4][4][4];
#pragma unroll
    for (int i = 0; i < 4; i++)
#pragma unroll
        for (int j = 0; j < 4; j++)
#pragma unroll
            for (int r = 0; r < 4; r++) acc[i][j][r] = 0.f;

    const int frow = tid >> 3;
    const int fcol = (tid & 7) * 4;
    const uint32_t soff = (uint32_t)frow * 80 + (uint32_t)(tid & 7) * 8;

    float4 pa[4], pb[4];
#pragma unroll
    for (int p = 0; p < 4; p++) {
        int row = p * 32 + frow;
        pa[p] = *(const float4*)(A  + (size_t)(m0 + row) * GK + fcol);
        pb[p] = *(const float4*)(Bw + (size_t)(n0 + row) * GK + fcol);
    }

    for (int kc = 0; kc < GK / 32; kc++) {
        const int buf = kc & 1;
        const uint32_t smA = sbase + buf * BUF_B;
        const uint32_t smB = smA + 2 * TILE_B;

#pragma unroll
        for (int p = 0; p < 4; p++) {
            uint32_t off = (uint32_t)p * 32 * 80 + soff;
            cvtsts(pa[p], smA + off, smA + TILE_B + off);
            cvtsts(pb[p], smB + off, smB + TILE_B + off);
        }
        __syncthreads();

        if (kc + 1 < GK / 32) {
            int col = fcol + (kc + 1) * 32;
#pragma unroll
            for (int p = 0; p < 4; p++) {
                int row = p * 32 + frow;
                pa[p] = *(const float4*)(A  + (size_t)(m0 + row) * GK + col);
                pb[p] = *(const float4*)(Bw + (size_t)(n0 + row) * GK + col);
            }
        }

#pragma unroll
        for (int ks = 0; ks < 2; ks++) {
            uint32_t af[4][4], bh[2][4], bl[2][4];
#pragma unroll
            for (int mf = 0; mf < 4; mf++) {
                uint32_t a = smA + ((uint32_t)(wm * 64 + mf * 16 + rowoff) * 40 + ks * 16 + koff) * 2;
                LDSM_X4(af[mf], a);
            }
#pragma unroll
            for (int nb = 0; nb < 2; nb++) {
                uint32_t b = smB + ((uint32_t)(wn * 32 + nb * 16 + rowoff) * 40 + ks * 16 + koff) * 2;
                LDSM_X4(bh[nb], b);
                LDSM_X4(bl[nb], b + TILE_B);
            }
#pragma unroll
            for (int mf = 0; mf < 4; mf++)
#pragma unroll
                for (int nf = 0; nf < 4; nf++) {
                    MMA16816(acc[mf][nf], af[mf], bh[nf >> 1][nf & 1], bh[nf >> 1][(nf & 1) + 2]);
                    MMA16816(acc[mf][nf], af[mf], bl[nf >> 1][nf & 1], bl[nf >> 1][(nf & 1) + 2]);
                }
#pragma unroll
            for (int mf = 0; mf < 4; mf++) {
                uint32_t a = smA + TILE_B + ((uint32_t)(wm * 64 + mf * 16 + rowoff) * 40 + ks * 16 + koff) * 2;
                LDSM_X4(af[mf], a);
            }
#pragma unroll
            for (int mf = 0; mf < 4; mf++)
#pragma unroll
                for (int nf = 0; nf < 4; nf++)
                    MMA16816(acc[mf][nf], af[mf], bh[nf >> 1][nf & 1], bh[nf >> 1][(nf & 1) + 2]);
        }
        __syncthreads();
    }

#pragma unroll
    for (int mf = 0; mf < 4; mf++) {
        int r0 = m0 + wm * 64 + mf * 16 + (lane >> 2);
#pragma unroll
        for (int nf = 0; nf < 4; nf++) {
            int c0 = n0 + wn * 32 + nf * 8 + (lane & 3) * 2;
            float2 v0 = make_float2(acc[mf][nf][0], acc[mf][nf][1]);
            float2 v1 = make_float2(acc[mf][nf][2], acc[mf][nf][3]);
            *(float2*)(C + (size_t)r0 * GN + c0)       = v0;
            *(float2*)(C + (size_t)(r0 + 8) * GN + c0) = v1;
        }
    }
}

// ================= RoPE ((b,s,h,d) layout) =================
__global__ void rope_kernel(float* __restrict__ q, float* __restrict__ k,
                            const float* __restrict__ cosT, const float* __restrict__ sinT) {
    int idx = blockIdx.x * blockDim.x + threadIdx.x;
    if (idx >= BB * SS * NHH * 32) return;
    int d = idx & 31;
    int r = idx >> 5;
    int s = (r >> 4) & (SS - 1);
    size_t base = (size_t)r * DD;
    float c1 = cosT[s * DD + d],      s1 = sinT[s * DD + d];
    float c2 = cosT[s * DD + d + 32], s2 = sinT[s * DD + d + 32];
    float x1 = q[base + d], x2 = q[base + d + 32];
    q[base + d]      = x1 * c1 - x2 * s1;
    q[base + d + 32] = x2 * c2 + x1 * s2;
    x1 = k[base + d]; x2 = k[base + d + 32];
    k[base + d]      = x1 * c1 - x2 * s1;
    k[base + d + 32] = x2 * c2 + x1 * s2;
}

// ================= per-chunk RFA summaries ((b,s,h,d)) =================
__global__ void __launch_bounds__(128) rfa_kernel(const float* __restrict__ k,
                                                  const float* __restrict__ v,
                                                  const float* __restrict__ mu,
                                                  const float* __restrict__ phi,
                                                  float* __restrict__ rk,
                                                  float* __restrict__ rv) {
    int bh = blockIdx.x / NCC;
    int c  = blockIdx.x % NCC;
    int b  = bh / NHH, h = bh % NHH;
    int j  = threadIdx.x;
    __shared__ float sb[CHUNKK], sg[CHUNKK];
    const float* kbase = k + (((size_t)b * SS + c * CHUNKK) * NHH + h) * DD;
    const float* vbase = v + (((size_t)b * SS + c * CHUNKK) * NHH + h) * DD;
    const float* kr = kbase + (size_t)j * HIDD;
    float dm = 0.f, dp = 0.f, nn = 0.f;
#pragma unroll
    for (int d = 0; d < DD; d++) {
        float kv = kr[d];
        dm += kv * mu[h * DD + d];
        dp += kv * phi[h * DD + d];
        nn += kv * kv;
    }
    float halfn = 0.5f * SCALEF * nn;
    sb[j] = SCALEF * dm - halfn;
    sg[j] = SCALEF * dp - halfn;
    __syncthreads();
    float mb = -1e30f, mg = -1e30f;
    for (int t = 0; t < CHUNKK; t++) { mb = fmaxf(mb, sb[t]); mg = fmaxf(mg, sg[t]); }
    float eb = expf(sb[j] - mb), eg = expf(sg[j] - mg);
    __syncthreads();
    sb[j] = eb; sg[j] = eg;
    __syncthreads();
    float zb = 0.f, zg = 0.f;
    for (int t = 0; t < CHUNKK; t++) { zb += sb[t]; zg += sg[t]; }
    float invb = 1.f / zb, invg = 1.f / zg;
    if (j < DD) {
        int d = j;
        float acc = 0.f;
        for (int t = 0; t < CHUNKK; t++) acc += sb[t] * kbase[(size_t)t * HIDD + d];
        rk[((size_t)bh * NCC + c) * DD + d] = acc * invb;
    } else {
        int d = j - DD;
        float acc = 0.f;
        for (int t = 0; t < CHUNKK; t++) acc += sg[t] * vbase[(size_t)t * HIDD + d];
        rv[((size_t)bh * NCC + c) * DD + d] = acc * invg;
    }
}

// ================= MMA flash attention =================
// smem: Qh[128][72], Ql, Kh[64][72], Kl, Vh[64][72], Vl (bf16)
#define AQ_H 0
#define AQ_L 18432
#define AK_H 36864
#define AK_L 46080
#define AV_H 55296
#define AV_L 64512
#define AT_SMEM 73728

// fill split tile: rows x 64 fp32 -> hi/lo bf16 smem [rows][72]
__device__ __forceinline__ void fill_split(const float* __restrict__ src, int rstride,
                                           int rows, int rlimit,
                                           uint32_t dhi, uint32_t dlo, int tid, float scale) {
    const int col4 = tid & 15;
    const int r0   = tid >> 4;
    for (int r = r0; r < rows; r += 8) {
        float4 f;
        if (r < rlimit) {
            f = *(const float4*)(src + (size_t)r * rstride + col4 * 4);
            f.x *= scale; f.y *= scale; f.z *= scale; f.w *= scale;
        } else {
            f = make_float4(0.f, 0.f, 0.f, 0.f);
        }
        uint32_t off = (uint32_t)r * 144 + col4 * 8;
        cvtsts(f, dhi + off, dlo + off);
    }
}

__global__ void __launch_bounds__(128, 2)
attn_mma(const float* __restrict__ q, const float* __restrict__ k,
         const float* __restrict__ v, const float* __restrict__ rk,
         const float* __restrict__ rv, float* __restrict__ out) {
    extern __shared__ char dsm[];
    const uint32_t sb = smem_u32(dsm);

    const int qt  = blockIdx.x;   // 0..3
    const int w   = blockIdx.y;   // 0..7
    const int bh  = blockIdx.z;   // 0..63
    const int b   = bh >> 4, h = bh & 15;
    const int tid = threadIdx.x, lane = tid & 31, wq = tid >> 5;

    const int rowoff = ((lane >> 3) & 1) * 8 + (lane & 7);
    const int koff   = (lane >> 4) * 8;
    // V trans-ldmatrix offsets
    const int vrow   = lane & 15;
    const int vnadd  = (lane >> 4) * 8;

    // fill Q (scaled by SCALEF)
    const float* qg = q + (((size_t)b * SS + w * WINN + qt * 128) * NHH + h) * DD;
    fill_split(qg, HIDD, 128, 128, sb + AQ_H, sb + AQ_L, tid, SCALEF);

    float OA[2][8][4];
#pragma unroll
    for (int mf = 0; mf < 2; mf++)
#pragma unroll
        for (int nf = 0; nf < 8; nf++)
#pragma unroll
            for (int r = 0; r < 4; r++) OA[mf][nf][r] = 0.f;
    float mrow[2][2] = {{-1e30f, -1e30f}, {-1e30f, -1e30f}};
    float lrow[2][2] = {{0.f, 0.f}, {0.f, 0.f}};

    const float* kwin = k + (((size_t)b * SS + w * WINN) * NHH + h) * DD;
    const float* vwin = v + (((size_t)b * SS + w * WINN) * NHH + h) * DD;
    const float* rkb  = rk + (size_t)bh * NCC * DD;
    const float* rvb  = rv + (size_t)bh * NCC * DD;

    const int nwt    = 2 * qt + 2;
    const int nch    = 4 * w;
    const int ntile  = nwt + (nch > 0 ? 1 : 0);

    for (int t = 0; t < ntile; t++) {
        const bool ischunk = (t == nwt);
        const int kt0 = t * 64;
        __syncthreads();
        if (!ischunk) {
            fill_split(kwin + (size_t)kt0 * HIDD, HIDD, 64, 64, sb + AK_H, sb + AK_L, tid, 1.f);
            fill_split(vwin + (size_t)kt0 * HIDD, HIDD, 64, 64, sb + AV_H, sb + AV_L, tid, 1.f);
        } else {
            fill_split(rkb, DD, 64, nch, sb + AK_H, sb + AK_L, tid, 1.f);
            fill_split(rvb, DD, 64, nch, sb + AV_H, sb + AV_L, tid, 1.f);
        }
        __syncthreads();

        // ---- S = Q * K^T (split-bf16, 3 passes) ----
        float SA[2][8][4];
#pragma unroll
        for (int mf = 0; mf < 2; mf++)
#pragma unroll
            for (int nf = 0; nf < 8; nf++)
#pragma unroll
                for (int r = 0; r < 4; r++) SA[mf][nf][r] = 0.f;

#pragma unroll
        for (int pass = 0; pass < 3; pass++) {
            const uint32_t Ab = sb + ((pass == 2) ? AQ_L : AQ_H);
            const uint32_t Bb = sb + ((pass == 1) ? AK_L : AK_H);
#pragma unroll
            for (int ks = 0; ks < 4; ks++) {
                uint32_t af[2][4], bf[4][4];
#pragma unroll
                for (int mf = 0; mf < 2; mf++)
                    LDSM_X4(af[mf], Ab + ((uint32_t)(wq * 32 + mf * 16 + rowoff) * 72 + ks * 16 + koff) * 2);
#pragma unroll
                for (int nb = 0; nb < 4; nb++)
                    LDSM_X4(bf[nb], Bb + ((uint32_t)(nb * 16 + rowoff) * 72 + ks * 16 + koff) * 2);
#pragma unroll
                for (int mf = 0; mf < 2; mf++)
#pragma unroll
                    for (int nf = 0; nf < 8; nf++)
                        MMA16816(SA[mf][nf], af[mf], bf[nf >> 1][nf & 1], bf[nf >> 1][(nf & 1) + 2]);
            }
        }

        // ---- mask ----
        if (ischunk) {
#pragma unroll
            for (int mf = 0; mf < 2; mf++)
#pragma unroll
                for (int nf = 0; nf < 8; nf++) {
                    int colb = nf * 8 + (lane & 3) * 2;
                    if (colb     >= nch) { SA[mf][nf][0] = -1e30f; SA[mf][nf][2] = -1e30f; }
                    if (colb + 1 >= nch) { SA[mf][nf][1] = -1e30f; SA[mf][nf][3] = -1e30f; }
                }
        } else if (t >= 2 * qt) {
#pragma unroll
            for (int mf = 0; mf < 2; mf++)
#pragma unroll
                for (int nf = 0; nf < 8; nf++) {
                    int colb = kt0 + nf * 8 + (lane & 3) * 2;
#pragma unroll
                    for (int hf = 0; hf < 2; hf++) {
                        int rowq = qt * 128 + wq * 32 + mf * 16 + (lane >> 2) + hf * 8;
                        if (colb     > rowq) SA[mf][nf][hf * 2]     = -1e30f;
                        if (colb + 1 > rowq) SA[mf][nf][hf * 2 + 1] = -1e30f;
                    }
                }
        }

        // ---- online softmax on fragments ----
#pragma unroll
        for (int mf = 0; mf < 2; mf++)
#pragma unroll
            for (int hf = 0; hf < 2; hf++) {
                float tm = -1e30f;
#pragma unroll
                for (int nf = 0; nf < 8; nf++) {
                    tm = fmaxf(tm, SA[mf][nf][hf * 2]);
                    tm = fmaxf(tm, SA[mf][nf][hf * 2 + 1]);
                }
                tm = fmaxf(tm, __shfl_xor_sync(0xFFFFFFFF, tm, 1));
                tm = fmaxf(tm, __shfl_xor_sync(0xFFFFFFFF, tm, 2));
                float mold = mrow[mf][hf];
                float mnew = fmaxf(mold, tm);
                float f = __expf(mold - mnew);
                float rs = 0.f;
#pragma unroll
                for (int nf = 0; nf < 8; nf++) {
                    float p0 = __expf(SA[mf][nf][hf * 2]     - mnew);
                    float p1 = __expf(SA[mf][nf][hf * 2 + 1] - mnew);
                    SA[mf][nf][hf * 2]     = p0;
                    SA[mf][nf][hf * 2 + 1] = p1;
                    rs += p0 + p1;
                }
                rs += __shfl_xor_sync(0xFFFFFFFF, rs, 1);
                rs += __shfl_xor_sync(0xFFFFFFFF, rs, 2);
                lrow[mf][hf] = lrow[mf][hf] * f + rs;
                mrow[mf][hf] = mnew;
#pragma unroll
                for (int nf = 0; nf < 8; nf++) {
                    OA[mf][nf][hf * 2]     *= f;
                    OA[mf][nf][hf * 2 + 1] *= f;
                }
            }

        // ---- O += P * V (PhVh + PlVh + PhVl) ----
#pragma unroll
        for (int kc = 0; kc < 4; kc++) {
            uint32_t ah[2][4], al[2][4];
#pragma unroll
            for (int mf = 0; mf < 2; mf++) {
                packsplit(SA[mf][2 * kc][0],     SA[mf][2 * kc][1],     ah[mf][0], al[mf][0]);
                packsplit(SA[mf][2 * kc][2],     SA[mf][2 * kc][3],     ah[mf][1], al[mf][1]);
                packsplit(SA[mf][2 * kc + 1][0], SA[mf][2 * kc + 1][1], ah[mf][2], al[mf][2]);
                packsplit(SA[mf][2 * kc + 1][2], SA[mf][2 * kc + 1][3], ah[mf][3], al[mf][3]);
            }
#pragma unroll
            for (int nq = 0; nq < 4; nq++) {
                uint32_t off = ((uint32_t)(kc * 16 + vrow) * 72 + nq * 16 + vnadd) * 2;
                uint32_t bv[4];
                LDSM_X4T(bv, sb + AV_H + off);
#pragma unroll
                for (int mf = 0; mf < 2; mf++) {
                    MMA16816R(OA[mf][2 * nq],     ah[mf][0], ah[mf][1], ah[mf][2], ah[mf][3], bv[0], bv[1]);
                    MMA16816R(OA[mf][2 * nq + 1], ah[mf][0], ah[mf][1], ah[mf][2], ah[mf][3], bv[2], bv[3]);
                    MMA16816R(OA[mf][2 * nq],     al[mf][0], al[mf][1], al[mf][2], al[mf][3], bv[0], bv[1]);
                    MMA16816R(OA[mf][2 * nq + 1], al[mf][0], al[mf][1], al[mf][2], al[mf][3], bv[2], bv[3]);
                }
                LDSM_X4T(bv, sb + AV_L + off);
#pragma unroll
                for (int mf = 0; mf < 2; mf++) {
                    MMA16816R(OA[mf][2 * nq],     ah[mf][0], ah[mf][1], ah[mf][2], ah[mf][3], bv[0], bv[1]);
                    MMA16816R(OA[mf][2 * nq + 1], ah[mf][0], ah[mf][1], ah[mf][2], ah[mf][3], bv[2], bv[3]);
                }
            }
        }
    }

    // ---- epilogue ----
#pragma unroll
    for (int mf = 0; mf < 2; mf++)
#pragma unroll
        for (int hf = 0; hf < 2; hf++) {
            float inv = 1.f / lrow[mf][hf];
            int row = w * WINN + qt * 128 + wq * 32 + mf * 16 + (lane >> 2) + hf * 8;
            float* orow = out + ((size_t)b * SS + row) * HIDD + h * DD;
#pragma unroll
            for (int nf = 0; nf < 8; nf++) {
                int d = nf * 8 + (lane & 3) * 2;
                float2 vv = make_float2(OA[mf][nf][hf * 2] * inv, OA[mf][nf][hf * 2 + 1] * inv);
                *(float2*)(orow + d) = vv;
            }
        }
}

// ---------------- launch ----------------
extern "C" void kernel_launch(void* const* d_in, const int* in_sizes, int n_in,
                              void* d_out, int out_size) {
    const float* hidden = (const float*)d_in[0];
    const float* Wq     = (const float*)d_in[1];
    const float* Wk     = (const float*)d_in[2];
    const float* Wv     = (const float*)d_in[3];
    const float* Wo     = (const float*)d_in[4];
    const float* mu     = (const float*)d_in[5];
    const float* phi    = (const float*)d_in[6];
    const float* cosT   = (const float*)d_in[7];
    const float* sinT   = (const float*)d_in[8];

    float *qb, *kb, *vb, *ab, *rkb, *rvb;
    cudaGetSymbolAddress((void**)&qb,  g_q);
    cudaGetSymbolAddress((void**)&kb,  g_k);
    cudaGetSymbolAddress((void**)&vb,  g_v);
    cudaGetSymbolAddress((void**)&ab,  g_attn);
    cudaGetSymbolAddress((void**)&rkb, g_rfak);
    cudaGetSymbolAddress((void**)&rvb, g_rfav);

    static bool attr_set = false;
    if (!attr_set) {
        cudaFuncSetAttribute((const void*)gemm_bf16s,
                             cudaFuncAttributeMaxDynamicSharedMemorySize, SMEM_DYN);
        cudaFuncSetAttribute((const void*)attn_mma,
                             cudaFuncAttributeMaxDynamicSharedMemorySize, AT_SMEM);
        attr_set = true;
    }

    dim3 ggrid(GN / 128, MTOK / 128);
    gemm_bf16s<<<ggrid, 256, SMEM_DYN>>>(hidden, Wq, qb);
    gemm_bf16s<<<ggrid, 256, SMEM_DYN>>>(hidden, Wk, kb);
    gemm_bf16s<<<ggrid, 256, SMEM_DYN>>>(hidden, Wv, vb);

    rope_kernel<<<(BB * SS * NHH * 32) / 256, 256>>>(qb, kb, cosT, sinT);

    rfa_kernel<<<BB * NHH * NCC, 128>>>(kb, vb, mu, phi, rkb, rvb);

    attn_mma<<<dim3(4, NWW, BB * NHH), 128, AT_SMEM>>>(qb, kb, vb, rkb, rvb, ab);

    gemm_bf16s<<<ggrid, 256, SMEM_DYN>>>(ab, Wo, (float*)d_out);
}